// round 6
// baseline (speedup 1.0000x reference)
#include <cuda_runtime.h>
#include <cuda_bf16.h>

// ---------------------------------------------------------------------------
// CAttention: B=8, N=2048, DIM=512, SCALE=1/8, 16 clusters.
// Pipeline:
//   1) qk   = x_token @ Wqk            [16384,1024]  (GEMM NN)
//   2) v    = x_token @ Wv             [16384,512]   (GEMM NN)
//   3) stable counting sort of idx_cluster per batch -> shuffle/restore/s/offs
//   4) attn_map[b] = q[b] @ k[b]^T * SCALE -> d_out (GEMM NT, batched)
//   5) e[b,j] = exp(attn_map[b, shuffle[shuffle[j]], j])
//   6) per-cluster weighted sums wsum[c][d] = sum e_j * v[shuffle[j]][d],
//      S[c] = sum e_j;  vsum[d] = sum_n v[n][d] (16 partials)
//   7) f[c][d] = (wsum + (EPS/N)*vsum) / (S + EPS)
//   8) out3[b,i,j] = f[ s[b,(r%4)*512+j] ][ r/4 ],  r = restore[b,i]
//   9) x_out = out3 @ Wproj + bproj -> d_out (GEMM NN + bias)
// No host-side CUDA API calls in kernel_launch except kernel launches.
// ---------------------------------------------------------------------------

#define BATCH 8
#define SEQ   2048
#define DIM   512
#define ROWS  (BATCH*SEQ)       // 16384
#define NCLUST 16
#define SCALE_F 0.125f
#define EPS_F  1e-6f

// -------------------- scratch (static device globals) ----------------------
__device__ float g_qk[(size_t)ROWS * 1024];     // 64 MB
__device__ float g_v[(size_t)ROWS * DIM];       // 32 MB
__device__ float g_out3[(size_t)ROWS * DIM];    // 32 MB
__device__ float g_e[BATCH * SEQ];
__device__ float g_S[BATCH * NCLUST];
__device__ float g_wsum[BATCH * NCLUST * DIM];
__device__ float g_vpart[BATCH * NCLUST * DIM];
__device__ float g_f[BATCH * NCLUST * DIM];
__device__ int   g_shuffle[BATCH * SEQ];
__device__ int   g_restore[BATCH * SEQ];
__device__ int   g_ssorted[BATCH * SEQ];
__device__ int   g_offs[BATCH * 17];

// Buffer selectors: -1 = use runtime pointer, 0 = g_qk, 1 = g_qk+DIM (k half),
// 2 = g_v, 3 = g_out3
template<int SEL>
__device__ __forceinline__ const float* pick_c(const float* p) {
    if (SEL == 0) return g_qk;
    if (SEL == 1) return g_qk + DIM;
    if (SEL == 2) return g_v;
    if (SEL == 3) return g_out3;
    return p;
}
template<int SEL>
__device__ __forceinline__ float* pick_m(float* p) {
    if (SEL == 0) return g_qk;
    if (SEL == 2) return g_v;
    if (SEL == 3) return g_out3;
    return p;
}

// -------------------------- tiled fp32 GEMM --------------------------------
// C[M,N] = alpha * A(M,K) * B(K,N or N,K if NT) (+ bias[n])
// BM=BN=128, BK=16, 256 threads, 8x8 microtile split as 2x2 blocks of 4x4.
#define GBM 128
#define GBN 128
#define GBK 16
#define TPAD 132

template<bool NT, bool BIAS, int ASEL, int BSEL, int CSEL>
__global__ __launch_bounds__(256)
void gemm_tile(const float* __restrict__ Ain, const float* __restrict__ Bin,
               float* __restrict__ Cin, const float* __restrict__ bias,
               int N, int K, int lda, int ldb, int ldc,
               size_t sA, size_t sB, size_t sC, float alpha)
{
    const float* A  = pick_c<ASEL>(Ain) + (size_t)blockIdx.z * sA;
    const float* Bm = pick_c<BSEL>(Bin) + (size_t)blockIdx.z * sB;
    float*       C  = pick_m<CSEL>(Cin) + (size_t)blockIdx.z * sC;

    const int m0 = blockIdx.y * GBM;
    const int n0 = blockIdx.x * GBN;

    __shared__ float As[GBK][TPAD];
    __shared__ float Bs[GBK][TPAD];

    const int tid = threadIdx.x;
    const int tx = tid & 15;        // 0..15
    const int ty = tid >> 4;        // 0..15

    float acc[8][8];
#pragma unroll
    for (int i = 0; i < 8; ++i)
#pragma unroll
        for (int j = 0; j < 8; ++j) acc[i][j] = 0.f;

    for (int k0 = 0; k0 < K; k0 += GBK) {
        // Load A tile (k-fast): BM*BK = 2048 elems / 256 thr = 8 each
#pragma unroll
        for (int l = 0; l < 8; ++l) {
            int idx = tid + l * 256;
            int k = idx & 15;
            int m = idx >> 4;
            As[k][m] = A[(size_t)(m0 + m) * lda + (k0 + k)];
        }
        // Load B tile
#pragma unroll
        for (int l = 0; l < 8; ++l) {
            int idx = tid + l * 256;
            if (NT) {
                int k = idx & 15;
                int n = idx >> 4;
                Bs[k][n] = Bm[(size_t)(n0 + n) * ldb + (k0 + k)];
            } else {
                int n = idx & 127;
                int k = idx >> 7;
                Bs[k][n] = Bm[(size_t)(k0 + k) * ldb + (n0 + n)];
            }
        }
        __syncthreads();

#pragma unroll
        for (int k = 0; k < GBK; ++k) {
            float a[8], b[8];
            *reinterpret_cast<float4*>(&a[0]) = *reinterpret_cast<const float4*>(&As[k][ty * 4]);
            *reinterpret_cast<float4*>(&a[4]) = *reinterpret_cast<const float4*>(&As[k][64 + ty * 4]);
            *reinterpret_cast<float4*>(&b[0]) = *reinterpret_cast<const float4*>(&Bs[k][tx * 4]);
            *reinterpret_cast<float4*>(&b[4]) = *reinterpret_cast<const float4*>(&Bs[k][64 + tx * 4]);
#pragma unroll
            for (int i = 0; i < 8; ++i)
#pragma unroll
                for (int j = 0; j < 8; ++j)
                    acc[i][j] += a[i] * b[j];
        }
        __syncthreads();
    }

    // Write out: rows (m0 + ib*64 + ty*4 + r), cols (n0 + jb*64 + tx*4)
#pragma unroll
    for (int ib = 0; ib < 2; ++ib)
#pragma unroll
    for (int r = 0; r < 4; ++r) {
        size_t m = (size_t)(m0 + ib * 64 + ty * 4 + r);
#pragma unroll
        for (int jb = 0; jb < 2; ++jb) {
            int n = n0 + jb * 64 + tx * 4;
            float4 v4;
            v4.x = alpha * acc[ib * 4 + r][jb * 4 + 0];
            v4.y = alpha * acc[ib * 4 + r][jb * 4 + 1];
            v4.z = alpha * acc[ib * 4 + r][jb * 4 + 2];
            v4.w = alpha * acc[ib * 4 + r][jb * 4 + 3];
            if (BIAS) {
                v4.x += bias[n + 0];
                v4.y += bias[n + 1];
                v4.z += bias[n + 2];
                v4.w += bias[n + 3];
            }
            *reinterpret_cast<float4*>(&C[m * ldc + n]) = v4;
        }
    }
}

// --------------------- stable counting sort (per batch) --------------------
__global__ void sort_kernel(const int* __restrict__ idx)
{
    int b = blockIdx.x;
    const int* ic = idx + b * SEQ;
    __shared__ int cnt[NCLUST];
    __shared__ int off[NCLUST + 1];
    int t = threadIdx.x;   // 32 threads

    if (t < NCLUST) {
        int c = 0;
        for (int i = 0; i < SEQ; ++i) c += (ic[i] == t);
        cnt[t] = c;
    }
    __syncthreads();
    if (t == 0) {
        int a = 0;
        for (int c = 0; c < NCLUST; ++c) { off[c] = a; a += cnt[c]; }
        off[NCLUST] = a;
        for (int c = 0; c <= NCLUST; ++c) g_offs[b * 17 + c] = off[c];
    }
    __syncthreads();
    if (t < NCLUST) {
        int pos = off[t];
        for (int i = 0; i < SEQ; ++i) {
            if (ic[i] == t) {
                g_shuffle[b * SEQ + pos] = i;
                g_restore[b * SEQ + i]  = pos;
                g_ssorted[b * SEQ + pos] = t;
                pos++;
            }
        }
    }
}

// ------------------------- e_j = exp(col_vals) -----------------------------
__global__ void ecol_kernel(const float* __restrict__ attn)
{
    int b = blockIdx.y;
    int j = blockIdx.x * 256 + threadIdx.x;
    const int* sh = g_shuffle + b * SEQ;
    int dd = sh[sh[j]];
    float val = attn[(size_t)b * SEQ * SEQ + (size_t)dd * SEQ + j];
    g_e[b * SEQ + j] = expf(val);
}

// --------------------- per-cluster weighted sums + vsum --------------------
__global__ void csum_kernel()
{
    int b = blockIdx.y;
    int c = blockIdx.x;     // 0..15 clusters, 16..31 vsum partials
    int d = threadIdx.x;    // 0..511
    const float* vb = g_v + (size_t)b * SEQ * DIM;

    if (c < NCLUST) {
        int j0 = g_offs[b * 17 + c];
        int j1 = g_offs[b * 17 + c + 1];
        float acc = 0.f, se = 0.f;
        for (int j = j0; j < j1; ++j) {
            float w = g_e[b * SEQ + j];
            int row = g_shuffle[b * SEQ + j];
            acc += w * vb[(size_t)row * DIM + d];
            se += w;
        }
        g_wsum[(b * NCLUST + c) * DIM + d] = acc;
        if (d == 0) g_S[b * NCLUST + c] = se;
    } else {
        int p = c - NCLUST;
        int j0 = p * 128, j1 = j0 + 128;
        float acc = 0.f;
        for (int j = j0; j < j1; ++j) acc += vb[(size_t)j * DIM + d];
        g_vpart[(b * NCLUST + p) * DIM + d] = acc;
    }
}

// ------------------- f[c][d] = (wsum + eps/N*vsum)/(S+eps) -----------------
__global__ void fcomp_kernel()
{
    int b = blockIdx.y, c = blockIdx.x, d = threadIdx.x;
    float vs = 0.f;
#pragma unroll
    for (int p = 0; p < NCLUST; ++p) vs += g_vpart[(b * NCLUST + p) * DIM + d];
    float w = g_wsum[(b * NCLUST + c) * DIM + d];
    g_f[(b * NCLUST + c) * DIM + d] = (w + (EPS_F / (float)SEQ) * vs) / (g_S[b * NCLUST + c] + EPS_F);
}

// --------- out3[b,i,j] = f[ s[b,(r%4)*512+j] ][ r/4 ],  r = restore --------
__global__ void gather_kernel()
{
    int b = blockIdx.z;
    int i = blockIdx.y;
    int j = blockIdx.x * 256 + threadIdx.x;
    int r = g_restore[b * SEQ + i];
    int cval = g_ssorted[b * SEQ + ((r & 3) << 9) + j];
    g_out3[((size_t)(b * SEQ + i)) * DIM + j] = g_f[(b * NCLUST + cval) * DIM + (r >> 2)];
}

// ---------------------------------------------------------------------------
extern "C" void kernel_launch(void* const* d_in, const int* in_sizes, int n_in,
                              void* d_out, int out_size)
{
    const float *x_token = nullptr, *Wqk = nullptr, *Wv = nullptr,
                *Wproj = nullptr, *bproj = nullptr;
    const int *idxc = nullptr;
    for (int i = 0; i < n_in; ++i) {
        long s = in_sizes[i];
        if (s == 8388608 && !x_token)      x_token = (const float*)d_in[i];
        else if (s == 16384 && !idxc)      idxc    = (const int*)d_in[i];
        else if (s == 524288 && !Wqk)      Wqk     = (const float*)d_in[i];
        else if (s == 262144) { if (!Wv) Wv = (const float*)d_in[i];
                                else if (!Wproj) Wproj = (const float*)d_in[i]; }
        else if (s == 512 && !bproj)       bproj   = (const float*)d_in[i];
    }
    if (!x_token || !idxc || !Wqk || !Wv || !Wproj || !bproj) return;

    float* xout = (float*)d_out;                         // [16384, 512]
    float* attn = xout + (size_t)ROWS * DIM;             // [8, 2048, 2048]

    // 1) qk = x_token @ Wqk   (M=16384, N=1024, K=512)  -> g_qk
    gemm_tile<false, false, -1, -1, 0><<<dim3(1024 / GBN, ROWS / GBM, 1), 256>>>(
        x_token, Wqk, nullptr, nullptr, 1024, DIM, DIM, 1024, 1024, 0, 0, 0, 1.0f);

    // 2) v = x_token @ Wv     (M=16384, N=512, K=512)   -> g_v
    gemm_tile<false, false, -1, -1, 2><<<dim3(DIM / GBN, ROWS / GBM, 1), 256>>>(
        x_token, Wv, nullptr, nullptr, DIM, DIM, DIM, DIM, DIM, 0, 0, 0, 1.0f);

    // 3) stable counting sort
    sort_kernel<<<BATCH, 32>>>(idxc);

    // 4) attn_map[b] = q[b] @ k[b]^T * SCALE  (batched NT, M=N=2048, K=512)
    //    A = g_qk (q half), B = g_qk + DIM (k half)
    gemm_tile<true, false, 0, 1, -1><<<dim3(SEQ / GBN, SEQ / GBM, BATCH), 256>>>(
        nullptr, nullptr, attn, nullptr, SEQ, DIM, 1024, 1024, SEQ,
        (size_t)SEQ * 1024, (size_t)SEQ * 1024, (size_t)SEQ * SEQ, SCALE_F);

    // 5) e_j
    ecol_kernel<<<dim3(SEQ / 256, BATCH), 256>>>(attn);

    // 6) cluster sums + vsum partials
    csum_kernel<<<dim3(32, BATCH), DIM>>>();

    // 7) f
    fcomp_kernel<<<dim3(NCLUST, BATCH), DIM>>>();

    // 8) gather/scramble into out3
    gather_kernel<<<dim3(DIM / 256, SEQ, BATCH), 256>>>();

    // 9) x_out = out3 @ Wproj + bproj  (M=16384, N=512, K=512), A = g_out3
    gemm_tile<false, true, 3, -1, -1><<<dim3(DIM / GBN, ROWS / GBM, 1), 256>>>(
        nullptr, Wproj, xout, bproj, DIM, DIM, DIM, DIM, DIM, 0, 0, 0, 1.0f);

    (void)out_size;
}

// round 8
// speedup vs baseline: 2.5899x; 2.5899x over previous
#include <cuda_runtime.h>
#include <cuda_bf16.h>
#include <cstdint>

// ---------------------------------------------------------------------------
// CAttention B=8,N=2048,DIM=512. GEMMs via mma.sync m16n8k8 tf32 (compute_103
// generic PTX — tcgen05 is unavailable in this harness's PTX target).
// Canonical GEMM: D[M,N] = alpha * A[M,K] @ B[N,K]^T (+bias), K=512.
// ---------------------------------------------------------------------------

#define BATCH 8
#define SEQ   2048
#define DIM   512
#define ROWS  (BATCH*SEQ)
#define NCLUST 16
#define SCALE_F 0.125f
#define EPS_F  1e-6f

__device__ float g_qk[(size_t)ROWS * 1024];
__device__ float g_v[(size_t)ROWS * DIM];
__device__ float g_out3[(size_t)ROWS * DIM];
__device__ float g_wqkT[1024 * 512];
__device__ float g_wvT[512 * 512];
__device__ float g_wprojT[512 * 512];
__device__ float g_e[BATCH * SEQ];
__device__ float g_S[BATCH * NCLUST];
__device__ float g_wsum[BATCH * NCLUST * DIM];
__device__ float g_vpart[BATCH * NCLUST * DIM];
__device__ float g_f[BATCH * NCLUST * DIM];
__device__ int   g_shuffle[BATCH * SEQ];
__device__ int   g_restore[BATCH * SEQ];
__device__ int   g_ssorted[BATCH * SEQ];
__device__ int   g_offs[BATCH * 17];

template<int SEL>
__device__ __forceinline__ const float* pick_c(const float* p) {
    if (SEL == 0) return g_qk;
    if (SEL == 1) return g_qk + DIM;
    if (SEL == 2) return g_v;
    if (SEL == 3) return g_out3;
    if (SEL == 4) return g_wqkT;
    if (SEL == 5) return g_wvT;
    if (SEL == 6) return g_wprojT;
    return p;
}
template<int SEL>
__device__ __forceinline__ float* pick_m(float* p) {
    if (SEL == 2) return g_v;
    if (SEL == 3) return g_out3;
    if (SEL == 0) return g_qk;
    if (SEL == 4) return g_wqkT;
    if (SEL == 5) return g_wvT;
    if (SEL == 6) return g_wprojT;
    return p;
}

__device__ __forceinline__ uint32_t f2tf32(float f) {
    uint32_t r;
    asm("cvt.rna.tf32.f32 %0, %1;" : "=r"(r) : "f"(f));
    return r;
}

// ------------------------- tf32 mma.sync GEMM -------------------------------
// BM=BN=128, BK=16, 256 threads (8 warps, 2x4), warp tile 64x32 (4x4 atoms).
// Smem: [128][20] per operand, double-buffered -> 40KB static.
#define BKT 16
#define SPAD 20
#define SBUF (128 * SPAD)         // u32 per operand per buffer

__device__ __forceinline__ void mma_tf32(float* c, const uint32_t* a, const uint32_t* b) {
    asm volatile(
        "mma.sync.aligned.m16n8k8.row.col.f32.tf32.tf32.f32 "
        "{%0,%1,%2,%3}, {%4,%5,%6,%7}, {%8,%9}, {%0,%1,%2,%3};"
        : "+f"(c[0]), "+f"(c[1]), "+f"(c[2]), "+f"(c[3])
        : "r"(a[0]), "r"(a[1]), "r"(a[2]), "r"(a[3]), "r"(b[0]), "r"(b[1]));
}

template<bool BIAS, int ASEL, int BSEL, int CSEL>
__global__ __launch_bounds__(256)
void gemm_mma(const float* __restrict__ Ain, const float* __restrict__ Bin,
              float* __restrict__ Cin, const float* __restrict__ bias,
              int lda, int ldb, int ldc,
              size_t sA, size_t sB, size_t sC, float alpha)
{
    __shared__ uint32_t sm[2][2 * SBUF];   // [buf][A then B]

    const float* A = pick_c<ASEL>(Ain) + (size_t)blockIdx.z * sA;
    const float* B = pick_c<BSEL>(Bin) + (size_t)blockIdx.z * sB;
    float*       C = pick_m<CSEL>(Cin) + (size_t)blockIdx.z * sC;

    const int m0 = blockIdx.y * 128;
    const int n0 = blockIdx.x * 128;
    const int tid  = threadIdx.x;
    const int warp = tid >> 5, lane = tid & 31;
    const int wm = (warp & 1) * 64;        // warp M offset
    const int wn = (warp >> 1) * 32;       // warp N offset
    const int gid = lane >> 2, tig = lane & 3;

    float acc[4][4][4];
#pragma unroll
    for (int i = 0; i < 4; ++i)
#pragma unroll
        for (int j = 0; j < 4; ++j)
#pragma unroll
            for (int r = 0; r < 4; ++r) acc[i][j][r] = 0.f;

    // staging regs: 2 float4 per operand per tile
    float4 rga[2], rgb[2];
    const int srow = tid >> 2;             // 0..63  (covers 128 rows via 2 iters)
    const int scol = (tid & 3) << 2;       // 0,4,8,12

    auto gload = [&](int k0) {
#pragma unroll
        for (int l = 0; l < 2; ++l) {
            int row = srow + l * 64;
            rga[l] = *reinterpret_cast<const float4*>(A + (size_t)(m0 + row) * lda + k0 + scol);
            rgb[l] = *reinterpret_cast<const float4*>(B + (size_t)(n0 + row) * ldb + k0 + scol);
        }
    };
    auto sstore = [&](int buf) {
        uint32_t* As = sm[buf];
        uint32_t* Bs = sm[buf] + SBUF;
#pragma unroll
        for (int l = 0; l < 2; ++l) {
            int row = srow + l * 64;
            uint32_t o = row * SPAD + scol;
            As[o + 0] = f2tf32(rga[l].x); As[o + 1] = f2tf32(rga[l].y);
            As[o + 2] = f2tf32(rga[l].z); As[o + 3] = f2tf32(rga[l].w);
            Bs[o + 0] = f2tf32(rgb[l].x); Bs[o + 1] = f2tf32(rgb[l].y);
            Bs[o + 2] = f2tf32(rgb[l].z); Bs[o + 3] = f2tf32(rgb[l].w);
        }
    };

    gload(0);
    sstore(0);
    __syncthreads();

    const int NIT = 512 / BKT;   // 32
    for (int it = 0; it < NIT; ++it) {
        if (it + 1 < NIT) gload((it + 1) * BKT);

        const uint32_t* As = sm[it & 1];
        const uint32_t* Bs = sm[it & 1] + SBUF;
#pragma unroll
        for (int ks = 0; ks < 2; ++ks) {
            const int k0 = ks * 8;
            uint32_t af[4][4], bf[4][2];
#pragma unroll
            for (int am = 0; am < 4; ++am) {
                int r = wm + am * 16;
                af[am][0] = As[(r + gid)     * SPAD + k0 + tig];
                af[am][1] = As[(r + gid + 8) * SPAD + k0 + tig];
                af[am][2] = As[(r + gid)     * SPAD + k0 + tig + 4];
                af[am][3] = As[(r + gid + 8) * SPAD + k0 + tig + 4];
            }
#pragma unroll
            for (int an = 0; an < 4; ++an) {
                int c = wn + an * 8;
                bf[an][0] = Bs[(c + gid) * SPAD + k0 + tig];
                bf[an][1] = Bs[(c + gid) * SPAD + k0 + tig + 4];
            }
#pragma unroll
            for (int am = 0; am < 4; ++am)
#pragma unroll
                for (int an = 0; an < 4; ++an)
                    mma_tf32(acc[am][an], af[am], bf[an]);
        }
        if (it + 1 < NIT) {
            sstore((it + 1) & 1);
        }
        __syncthreads();
    }

    // epilogue
#pragma unroll
    for (int am = 0; am < 4; ++am) {
        int row = m0 + wm + am * 16 + gid;
#pragma unroll
        for (int an = 0; an < 4; ++an) {
            int col = n0 + wn + an * 8 + 2 * tig;
            float b0 = 0.f, b1 = 0.f;
            if (BIAS) { b0 = bias[col]; b1 = bias[col + 1]; }
            float2 v0, v1;
            v0.x = acc[am][an][0] * alpha + b0;
            v0.y = acc[am][an][1] * alpha + b1;
            v1.x = acc[am][an][2] * alpha + b0;
            v1.y = acc[am][an][3] * alpha + b1;
            *reinterpret_cast<float2*>(C + (size_t)row * ldc + col) = v0;
            *reinterpret_cast<float2*>(C + (size_t)(row + 8) * ldc + col) = v1;
        }
    }
}

// -------------------------- weight transpose -------------------------------
template<int DSTSEL>
__global__ void transpose_k(const float* __restrict__ in, int R, int C)
{
    __shared__ float t[32][33];
    float* out = pick_m<DSTSEL>(nullptr);
    int c0 = blockIdx.x * 32, r0 = blockIdx.y * 32;
    int x = threadIdx.x, y = threadIdx.y;  // 32 x 8
#pragma unroll
    for (int i = 0; i < 32; i += 8)
        t[y + i][x] = in[(size_t)(r0 + y + i) * C + (c0 + x)];
    __syncthreads();
#pragma unroll
    for (int i = 0; i < 32; i += 8)
        out[(size_t)(c0 + y + i) * R + (r0 + x)] = t[x][y + i];
}

// --------------------- stable counting sort (per batch) --------------------
__global__ void sort_kernel(const int* __restrict__ idx)
{
    int b = blockIdx.x;
    const int* ic = idx + b * SEQ;
    __shared__ int cnt[NCLUST];
    __shared__ int off[NCLUST + 1];
    int t = threadIdx.x;
    if (t < NCLUST) {
        int c = 0;
        for (int i = 0; i < SEQ; ++i) c += (ic[i] == t);
        cnt[t] = c;
    }
    __syncthreads();
    if (t == 0) {
        int a = 0;
        for (int c = 0; c < NCLUST; ++c) { off[c] = a; a += cnt[c]; }
        off[NCLUST] = a;
        for (int c = 0; c <= NCLUST; ++c) g_offs[b * 17 + c] = off[c];
    }
    __syncthreads();
    if (t < NCLUST) {
        int pos = off[t];
        for (int i = 0; i < SEQ; ++i)
            if (ic[i] == t) {
                g_shuffle[b * SEQ + pos] = i;
                g_restore[b * SEQ + i] = pos;
                g_ssorted[b * SEQ + pos] = t;
                pos++;
            }
    }
}

__global__ void ecol_kernel(const float* __restrict__ attn)
{
    int b = blockIdx.y;
    int j = blockIdx.x * 256 + threadIdx.x;
    const int* sh = g_shuffle + b * SEQ;
    int dd = sh[sh[j]];
    g_e[b * SEQ + j] = expf(attn[(size_t)b * SEQ * SEQ + (size_t)dd * SEQ + j]);
}

__global__ void csum_kernel()
{
    int b = blockIdx.y, c = blockIdx.x, d = threadIdx.x;
    const float* vb = g_v + (size_t)b * SEQ * DIM;
    if (c < NCLUST) {
        int j0 = g_offs[b * 17 + c], j1 = g_offs[b * 17 + c + 1];
        float acc = 0.f, se = 0.f;
        for (int j = j0; j < j1; ++j) {
            float w = g_e[b * SEQ + j];
            int row = g_shuffle[b * SEQ + j];
            acc += w * vb[(size_t)row * DIM + d];
            se += w;
        }
        g_wsum[(b * NCLUST + c) * DIM + d] = acc;
        if (d == 0) g_S[b * NCLUST + c] = se;
    } else {
        int p = c - NCLUST;
        float acc = 0.f;
        for (int j = p * 128; j < p * 128 + 128; ++j)
            acc += vb[(size_t)j * DIM + d];
        g_vpart[(b * NCLUST + p) * DIM + d] = acc;
    }
}

__global__ void fcomp_kernel()
{
    int b = blockIdx.y, c = blockIdx.x, d = threadIdx.x;
    float vs = 0.f;
#pragma unroll
    for (int p = 0; p < NCLUST; ++p) vs += g_vpart[(b * NCLUST + p) * DIM + d];
    float w = g_wsum[(b * NCLUST + c) * DIM + d];
    g_f[(b * NCLUST + c) * DIM + d] =
        (w + (EPS_F / (float)SEQ) * vs) / (g_S[b * NCLUST + c] + EPS_F);
}

__global__ void gather_kernel()
{
    int b = blockIdx.z, i = blockIdx.y;
    int j = blockIdx.x * 256 + threadIdx.x;
    int r = g_restore[b * SEQ + i];
    int cval = g_ssorted[b * SEQ + ((r & 3) << 9) + j];
    g_out3[((size_t)(b * SEQ + i)) * DIM + j] = g_f[(b * NCLUST + cval) * DIM + (r >> 2)];
}

// ---------------------------------------------------------------------------
extern "C" void kernel_launch(void* const* d_in, const int* in_sizes, int n_in,
                              void* d_out, int out_size)
{
    const float *x_token = nullptr, *Wqk = nullptr, *Wv = nullptr,
                *Wproj = nullptr, *bproj = nullptr;
    const int *idxc = nullptr;
    for (int i = 0; i < n_in; ++i) {
        long s = in_sizes[i];
        if (s == 8388608 && !x_token)      x_token = (const float*)d_in[i];
        else if (s == 16384 && !idxc)      idxc    = (const int*)d_in[i];
        else if (s == 524288 && !Wqk)      Wqk     = (const float*)d_in[i];
        else if (s == 262144) { if (!Wv) Wv = (const float*)d_in[i];
                                else if (!Wproj) Wproj = (const float*)d_in[i]; }
        else if (s == 512 && !bproj)       bproj   = (const float*)d_in[i];
    }
    if (!x_token || !idxc || !Wqk || !Wv || !Wproj || !bproj) return;

    float* xout = (float*)d_out;
    float* attn = xout + (size_t)ROWS * DIM;

    // 0) transpose weights to K-major [N, K]
    transpose_k<4><<<dim3(1024 / 32, 512 / 32), dim3(32, 8)>>>(Wqk, 512, 1024);
    transpose_k<5><<<dim3(512 / 32, 512 / 32), dim3(32, 8)>>>(Wv, 512, 512);
    transpose_k<6><<<dim3(512 / 32, 512 / 32), dim3(32, 8)>>>(Wproj, 512, 512);

    // 1) qk = x_token @ Wqk  (M=16384, N=1024, K=512) -> g_qk
    gemm_mma<false, -1, 4, 0><<<dim3(8, 128, 1), 256>>>(
        x_token, nullptr, nullptr, nullptr, 512, 512, 1024, 0, 0, 0, 1.0f);

    // 2) v = x_token @ Wv -> g_v
    gemm_mma<false, -1, 5, 2><<<dim3(4, 128, 1), 256>>>(
        x_token, nullptr, nullptr, nullptr, 512, 512, 512, 0, 0, 0, 1.0f);

    // 3) sort
    sort_kernel<<<BATCH, 32>>>(idxc);

    // 4) attn[b] = q[b] @ k[b]^T * SCALE  (batched)
    gemm_mma<false, 0, 1, -1><<<dim3(16, 16, BATCH), 256>>>(
        nullptr, nullptr, attn, nullptr, 1024, 1024, SEQ,
        (size_t)SEQ * 1024, (size_t)SEQ * 1024, (size_t)SEQ * SEQ, SCALE_F);

    // 5-8) elementwise pipeline
    ecol_kernel<<<dim3(SEQ / 256, BATCH), 256>>>(attn);
    csum_kernel<<<dim3(32, BATCH), DIM>>>();
    fcomp_kernel<<<dim3(NCLUST, BATCH), DIM>>>();
    gather_kernel<<<dim3(DIM / 256, SEQ, BATCH), 256>>>();

    // 9) x_out = out3 @ Wproj + bproj
    gemm_mma<true, 3, 6, -1><<<dim3(4, 128, 1), 256>>>(
        nullptr, nullptr, xout, bproj, 512, 512, 512, 0, 0, 0, 1.0f);

    (void)out_size;
}

// round 9
// speedup vs baseline: 2.9222x; 1.1283x over previous
#include <cuda_runtime.h>
#include <cuda_bf16.h>
#include <cstdint>

// ---------------------------------------------------------------------------
// CAttention B=8,N=2048,DIM=512. GEMMs via mma.sync m16n8k8 tf32 + ldmatrix
// fragment loads (compute_103-safe; tcgen05 unavailable in this harness).
// Canonical GEMM: D[M,N] = alpha * A[M,K] @ B[N,K]^T (+bias), K=512.
// ---------------------------------------------------------------------------

#define BATCH 8
#define SEQ   2048
#define DIM   512
#define ROWS  (BATCH*SEQ)
#define NCLUST 16
#define SCALE_F 0.125f
#define EPS_F  1e-6f

__device__ float g_qk[(size_t)ROWS * 1024];
__device__ float g_v[(size_t)ROWS * DIM];
__device__ float g_out3[(size_t)ROWS * DIM];
__device__ float g_wqkT[1024 * 512];
__device__ float g_wvT[512 * 512];
__device__ float g_wprojT[512 * 512];
__device__ float g_e[BATCH * SEQ];
__device__ float g_S[BATCH * NCLUST];
__device__ float g_wsum[BATCH * NCLUST * DIM];
__device__ float g_vpart[BATCH * NCLUST * DIM];
__device__ float g_f[BATCH * NCLUST * DIM];
__device__ int   g_shuffle[BATCH * SEQ];
__device__ int   g_restore[BATCH * SEQ];
__device__ int   g_ssorted[BATCH * SEQ];
__device__ int   g_offs[BATCH * 17];

template<int SEL>
__device__ __forceinline__ const float* pick_c(const float* p) {
    if (SEL == 0) return g_qk;
    if (SEL == 1) return g_qk + DIM;
    if (SEL == 2) return g_v;
    if (SEL == 3) return g_out3;
    if (SEL == 4) return g_wqkT;
    if (SEL == 5) return g_wvT;
    if (SEL == 6) return g_wprojT;
    return p;
}
template<int SEL>
__device__ __forceinline__ float* pick_m(float* p) {
    if (SEL == 0) return g_qk;
    if (SEL == 2) return g_v;
    if (SEL == 3) return g_out3;
    if (SEL == 4) return g_wqkT;
    if (SEL == 5) return g_wvT;
    if (SEL == 6) return g_wprojT;
    return p;
}

__device__ __forceinline__ uint32_t f2tf32(float f) {
    uint32_t r;
    asm("cvt.rna.tf32.f32 %0, %1;" : "=r"(r) : "f"(f));
    return r;
}
__device__ __forceinline__ uint32_t smem_u32(const void* p) {
    uint32_t a;
    asm("{ .reg .u64 t; cvta.to.shared.u64 t, %1; cvt.u32.u64 %0, t; }"
        : "=r"(a) : "l"(p));
    return a;
}

#define LDSM_X4(r, a) \
    asm volatile("ldmatrix.sync.aligned.m8n8.x4.shared.b16 {%0,%1,%2,%3}, [%4];" \
        : "=r"((r)[0]), "=r"((r)[1]), "=r"((r)[2]), "=r"((r)[3]) : "r"(a))

// ------------------------- tf32 mma.sync GEMM -------------------------------
// BM=BN=128, BK=16, 256 threads (8 warps, 2x4), warp tile 64x32 (4x4 atoms).
// Smem [128][20] u32 per operand, double-buffered -> 40KB static.
// Fragments loaded with ldmatrix.x4 (SPAD=20 keeps LDSM phases conflict-free).
#define BKT 16
#define SPAD 20
#define SBUF (128 * SPAD)

__device__ __forceinline__ void mma_tf32(float* c, const uint32_t* a,
                                         uint32_t b0, uint32_t b1) {
    asm volatile(
        "mma.sync.aligned.m16n8k8.row.col.f32.tf32.tf32.f32 "
        "{%0,%1,%2,%3}, {%4,%5,%6,%7}, {%8,%9}, {%0,%1,%2,%3};"
        : "+f"(c[0]), "+f"(c[1]), "+f"(c[2]), "+f"(c[3])
        : "r"(a[0]), "r"(a[1]), "r"(a[2]), "r"(a[3]), "r"(b0), "r"(b1));
}

template<bool BIAS, int ASEL, int BSEL, int CSEL>
__global__ __launch_bounds__(256)
void gemm_mma(const float* __restrict__ Ain, const float* __restrict__ Bin,
              float* __restrict__ Cin, const float* __restrict__ bias,
              int lda, int ldb, int ldc,
              size_t sA, size_t sB, size_t sC, float alpha)
{
    __shared__ uint32_t sm[2][2 * SBUF];

    const float* A = pick_c<ASEL>(Ain) + (size_t)blockIdx.z * sA;
    const float* B = pick_c<BSEL>(Bin) + (size_t)blockIdx.z * sB;
    float*       C = pick_m<CSEL>(Cin) + (size_t)blockIdx.z * sC;

    const int m0 = blockIdx.y * 128;
    const int n0 = blockIdx.x * 128;
    const int tid  = threadIdx.x;
    const int warp = tid >> 5, lane = tid & 31;
    const int wm = (warp & 1) * 64;
    const int wn = (warp >> 1) * 32;
    const int gid = lane >> 2, tig = lane & 3;

    // LDSM lane-address components
    const int i8 = lane & 7, mtx = lane >> 3;
    // A atom am (16x8): m0=rows+0 cols 0-3, m1=rows+8 cols 0-3, m2=rows+0 cols 4-7, m3=rows+8 cols 4-7
    int aoff[4];
#pragma unroll
    for (int am = 0; am < 4; ++am)
        aoff[am] = (wm + am * 16 + i8 + ((mtx & 1) << 3)) * SPAD + ((mtx >> 1) << 2);
    // B atom-pair bp covers atoms 2bp,2bp+1 (8 n-rows each):
    // m0=rows+0 cols 0-3, m1=rows+0 cols 4-7, m2=rows+8 cols 0-3, m3=rows+8 cols 4-7
    int boff[2];
#pragma unroll
    for (int bp = 0; bp < 2; ++bp)
        boff[bp] = (wn + bp * 16 + i8 + ((mtx >> 1) << 3)) * SPAD + ((mtx & 1) << 2);

    const uint32_t smbase = smem_u32(sm);

    float acc[4][4][4];
#pragma unroll
    for (int i = 0; i < 4; ++i)
#pragma unroll
        for (int j = 0; j < 4; ++j)
#pragma unroll
            for (int r = 0; r < 4; ++r) acc[i][j][r] = 0.f;

    float4 rga[2], rgb[2];
    const int srow = tid >> 2;
    const int scol = (tid & 3) << 2;

    auto gload = [&](int k0) {
#pragma unroll
        for (int l = 0; l < 2; ++l) {
            int row = srow + l * 64;
            rga[l] = *reinterpret_cast<const float4*>(A + (size_t)(m0 + row) * lda + k0 + scol);
            rgb[l] = *reinterpret_cast<const float4*>(B + (size_t)(n0 + row) * ldb + k0 + scol);
        }
    };
    auto sstore = [&](int buf) {
        uint32_t* As = sm[buf];
        uint32_t* Bs = sm[buf] + SBUF;
#pragma unroll
        for (int l = 0; l < 2; ++l) {
            int row = srow + l * 64;
            uint32_t o = row * SPAD + scol;
            As[o + 0] = f2tf32(rga[l].x); As[o + 1] = f2tf32(rga[l].y);
            As[o + 2] = f2tf32(rga[l].z); As[o + 3] = f2tf32(rga[l].w);
            Bs[o + 0] = f2tf32(rgb[l].x); Bs[o + 1] = f2tf32(rgb[l].y);
            Bs[o + 2] = f2tf32(rgb[l].z); Bs[o + 3] = f2tf32(rgb[l].w);
        }
    };

    gload(0);
    sstore(0);
    __syncthreads();

    const int NIT = 512 / BKT;
    for (int it = 0; it < NIT; ++it) {
        if (it + 1 < NIT) gload((it + 1) * BKT);

        const uint32_t asA = smbase + (uint32_t)(it & 1) * (2 * SBUF * 4);
        const uint32_t asB = asA + SBUF * 4;
#pragma unroll
        for (int ks = 0; ks < 2; ++ks) {
            const int k0 = ks * 8;
            uint32_t af[4][4], bf[2][4];
#pragma unroll
            for (int am = 0; am < 4; ++am)
                LDSM_X4(af[am], asA + (uint32_t)(aoff[am] + k0) * 4u);
#pragma unroll
            for (int bp = 0; bp < 2; ++bp)
                LDSM_X4(bf[bp], asB + (uint32_t)(boff[bp] + k0) * 4u);
#pragma unroll
            for (int am = 0; am < 4; ++am)
#pragma unroll
                for (int an = 0; an < 4; ++an)
                    mma_tf32(acc[am][an], af[am],
                             bf[an >> 1][(an & 1) * 2], bf[an >> 1][(an & 1) * 2 + 1]);
        }
        if (it + 1 < NIT) sstore((it + 1) & 1);
        __syncthreads();
    }

    // epilogue
#pragma unroll
    for (int am = 0; am < 4; ++am) {
        int row = m0 + wm + am * 16 + gid;
#pragma unroll
        for (int an = 0; an < 4; ++an) {
            int col = n0 + wn + an * 8 + 2 * tig;
            float b0 = 0.f, b1 = 0.f;
            if (BIAS) { b0 = bias[col]; b1 = bias[col + 1]; }
            float2 v0, v1;
            v0.x = acc[am][an][0] * alpha + b0;
            v0.y = acc[am][an][1] * alpha + b1;
            v1.x = acc[am][an][2] * alpha + b0;
            v1.y = acc[am][an][3] * alpha + b1;
            *reinterpret_cast<float2*>(C + (size_t)row * ldc + col) = v0;
            *reinterpret_cast<float2*>(C + (size_t)(row + 8) * ldc + col) = v1;
        }
    }
}

// -------------------------- weight transpose -------------------------------
template<int DSTSEL>
__global__ void transpose_k(const float* __restrict__ in, int R, int C)
{
    __shared__ float t[32][33];
    float* out = pick_m<DSTSEL>(nullptr);
    int c0 = blockIdx.x * 32, r0 = blockIdx.y * 32;
    int x = threadIdx.x, y = threadIdx.y;
#pragma unroll
    for (int i = 0; i < 32; i += 8)
        t[y + i][x] = in[(size_t)(r0 + y + i) * C + (c0 + x)];
    __syncthreads();
#pragma unroll
    for (int i = 0; i < 32; i += 8)
        out[(size_t)(c0 + y + i) * R + (r0 + x)] = t[x][y + i];
}

// --------------------- stable counting sort (per batch) --------------------
__global__ void sort_kernel(const int* __restrict__ idx)
{
    int b = blockIdx.x;
    const int* ic = idx + b * SEQ;
    __shared__ int cnt[NCLUST];
    __shared__ int off[NCLUST + 1];
    int t = threadIdx.x;
    if (t < NCLUST) {
        int c = 0;
        for (int i = 0; i < SEQ; ++i) c += (ic[i] == t);
        cnt[t] = c;
    }
    __syncthreads();
    if (t == 0) {
        int a = 0;
        for (int c = 0; c < NCLUST; ++c) { off[c] = a; a += cnt[c]; }
        off[NCLUST] = a;
        for (int c = 0; c <= NCLUST; ++c) g_offs[b * 17 + c] = off[c];
    }
    __syncthreads();
    if (t < NCLUST) {
        int pos = off[t];
        for (int i = 0; i < SEQ; ++i)
            if (ic[i] == t) {
                g_shuffle[b * SEQ + pos] = i;
                g_restore[b * SEQ + i] = pos;
                g_ssorted[b * SEQ + pos] = t;
                pos++;
            }
    }
}

__global__ void ecol_kernel(const float* __restrict__ attn)
{
    int b = blockIdx.y;
    int j = blockIdx.x * 256 + threadIdx.x;
    const int* sh = g_shuffle + b * SEQ;
    int dd = sh[sh[j]];
    g_e[b * SEQ + j] = expf(attn[(size_t)b * SEQ * SEQ + (size_t)dd * SEQ + j]);
}

__global__ void csum_kernel()
{
    int b = blockIdx.y, c = blockIdx.x, d = threadIdx.x;
    const float* vb = g_v + (size_t)b * SEQ * DIM;
    if (c < NCLUST) {
        int j0 = g_offs[b * 17 + c], j1 = g_offs[b * 17 + c + 1];
        float acc = 0.f, se = 0.f;
        for (int j = j0; j < j1; ++j) {
            float w = g_e[b * SEQ + j];
            int row = g_shuffle[b * SEQ + j];
            acc += w * vb[(size_t)row * DIM + d];
            se += w;
        }
        g_wsum[(b * NCLUST + c) * DIM + d] = acc;
        if (d == 0) g_S[b * NCLUST + c] = se;
    } else {
        int p = c - NCLUST;
        float acc = 0.f;
        for (int j = p * 128; j < p * 128 + 128; ++j)
            acc += vb[(size_t)j * DIM + d];
        g_vpart[(b * NCLUST + p) * DIM + d] = acc;
    }
}

__global__ void fcomp_kernel()
{
    int b = blockIdx.y, c = blockIdx.x, d = threadIdx.x;
    float vs = 0.f;
#pragma unroll
    for (int p = 0; p < NCLUST; ++p) vs += g_vpart[(b * NCLUST + p) * DIM + d];
    float w = g_wsum[(b * NCLUST + c) * DIM + d];
    g_f[(b * NCLUST + c) * DIM + d] =
        (w + (EPS_F / (float)SEQ) * vs) / (g_S[b * NCLUST + c] + EPS_F);
}

__global__ void gather_kernel()
{
    int b = blockIdx.z, i = blockIdx.y;
    int j = blockIdx.x * 256 + threadIdx.x;
    int r = g_restore[b * SEQ + i];
    int cval = g_ssorted[b * SEQ + ((r & 3) << 9) + j];
    g_out3[((size_t)(b * SEQ + i)) * DIM + j] = g_f[(b * NCLUST + cval) * DIM + (r >> 2)];
}

// ---------------------------------------------------------------------------
extern "C" void kernel_launch(void* const* d_in, const int* in_sizes, int n_in,
                              void* d_out, int out_size)
{
    const float *x_token = nullptr, *Wqk = nullptr, *Wv = nullptr,
                *Wproj = nullptr, *bproj = nullptr;
    const int *idxc = nullptr;
    for (int i = 0; i < n_in; ++i) {
        long s = in_sizes[i];
        if (s == 8388608 && !x_token)      x_token = (const float*)d_in[i];
        else if (s == 16384 && !idxc)      idxc    = (const int*)d_in[i];
        else if (s == 524288 && !Wqk)      Wqk     = (const float*)d_in[i];
        else if (s == 262144) { if (!Wv) Wv = (const float*)d_in[i];
                                else if (!Wproj) Wproj = (const float*)d_in[i]; }
        else if (s == 512 && !bproj)       bproj   = (const float*)d_in[i];
    }
    if (!x_token || !idxc || !Wqk || !Wv || !Wproj || !bproj) return;

    float* xout = (float*)d_out;
    float* attn = xout + (size_t)ROWS * DIM;

    // 0) transpose weights to K-major [N, K]
    transpose_k<4><<<dim3(1024 / 32, 512 / 32), dim3(32, 8)>>>(Wqk, 512, 1024);
    transpose_k<5><<<dim3(512 / 32, 512 / 32), dim3(32, 8)>>>(Wv, 512, 512);
    transpose_k<6><<<dim3(512 / 32, 512 / 32), dim3(32, 8)>>>(Wproj, 512, 512);

    // 1) qk = x_token @ Wqk  -> g_qk
    gemm_mma<false, -1, 4, 0><<<dim3(8, 128, 1), 256>>>(
        x_token, nullptr, nullptr, nullptr, 512, 512, 1024, 0, 0, 0, 1.0f);

    // 2) v = x_token @ Wv -> g_v
    gemm_mma<false, -1, 5, 2><<<dim3(4, 128, 1), 256>>>(
        x_token, nullptr, nullptr, nullptr, 512, 512, 512, 0, 0, 0, 1.0f);

    // 3) sort
    sort_kernel<<<BATCH, 32>>>(idxc);

    // 4) attn[b] = q[b] @ k[b]^T * SCALE  (batched)
    gemm_mma<false, 0, 1, -1><<<dim3(16, 16, BATCH), 256>>>(
        nullptr, nullptr, attn, nullptr, 1024, 1024, SEQ,
        (size_t)SEQ * 1024, (size_t)SEQ * 1024, (size_t)SEQ * SEQ, SCALE_F);

    // 5-8) elementwise pipeline
    ecol_kernel<<<dim3(SEQ / 256, BATCH), 256>>>(attn);
    csum_kernel<<<dim3(32, BATCH), DIM>>>();
    fcomp_kernel<<<dim3(NCLUST, BATCH), DIM>>>();
    gather_kernel<<<dim3(DIM / 256, SEQ, BATCH), 256>>>();

    // 9) x_out = out3 @ Wproj + bproj
    gemm_mma<true, 3, 6, -1><<<dim3(4, 128, 1), 256>>>(
        nullptr, nullptr, xout, bproj, 512, 512, 512, 0, 0, 0, 1.0f);

    (void)out_size;
}